// round 12
// baseline (speedup 1.0000x reference)
#include <cuda_runtime.h>
#include <cstdint>

// Temporal_Attention — weight-space-collapsed, cluster-free.
// k_pre: weight-only precompute (G', ub', gb', dq', M, cbias, S); PDL trigger
//        at entry so k_main overlaps it.
// k_main: ONE CTA per batch, grid 64 x 1024 thr, ~186 KB smem, no clusters,
//         no DSMEM, full softmax in-CTA. Phases separated by bar.sync only.
// B=64, T=256, D=128, H=8, E=128.  out[B,D] fp32.

#define BB 64
#define TT 256
#define DD 128
#define HH 8
#define HE 1024
#define SCALE 0.088388347648318447f

static __device__ float g_S;
static __device__ __align__(16) float g_G[HH * DD * DD];   // [h][dp][d]
static __device__ __align__(16) float g_ub[HH * DD];
static __device__ __align__(16) float g_gb[HH * DD];
static __device__ float g_dqs[HH];
static __device__ __align__(16) float g_M[HE * DD];        // [k][d2]
static __device__ __align__(16) float g_cbp[8 * DD];

// ---- helpers ---------------------------------------------------------------
__device__ __forceinline__ void ffma2(unsigned long long& d,
                                      unsigned long long a, unsigned long long b) {
    asm("fma.rn.f32x2 %0, %1, %2, %0;" : "+l"(d) : "l"(a), "l"(b));
}
__device__ __forceinline__ unsigned long long pk2(float x, float y) {
    unsigned long long r;
    asm("mov.b64 %0, {%1, %2};" : "=l"(r) : "f"(x), "f"(y));
    return r;
}
__device__ __forceinline__ float2 upk2(unsigned long long v) {
    float lo, hi;
    asm("mov.b64 {%0, %1}, %2;" : "=f"(lo), "=f"(hi) : "l"(v));
    return make_float2(lo, hi);
}
__device__ __forceinline__ float dot4(float4 a, float4 b) {
    return a.x * b.x + a.y * b.y + a.z * b.z + a.w * b.w;
}

// ===========================================================================
// K1: grid 145 x 256.  roles: G(0-63) | M(64-127) | gb(128-135)
//                             | cbias(136-143) | misc(144)
__global__ __launch_bounds__(256) void k_pre(
    const float* __restrict__ Ws,
    const float* __restrict__ Wk, const float* __restrict__ bk,
    const float* __restrict__ Wq, const float* __restrict__ bq,
    const float* __restrict__ Wv, const float* __restrict__ bv,
    const float* __restrict__ Wo, const float* __restrict__ bo)
{
    cudaTriggerProgrammaticLaunchCompletion();

    __shared__ __align__(16) float s[12288];   // 48 KB
    const int blk = blockIdx.x, tid = threadIdx.x;

    if (blk < 64) {
        // ------------- G role: G'[h, r0..r0+15, :] (+ub on rt==0) -------------
        const int w = blk, h = w >> 3, rt = w & 7, r0 = rt * 16;
        const int d2 = tid & 127, rg = tid >> 7;
        float4* wq4s = (float4*)s;            // [128][17] float4
        float4* wk4s = (float4*)(s + 8704);   // [16][16]
        float4* bk4s = (float4*)(s + 9728);   // [16]
        const float4* Wq4 = (const float4*)Wq;
        const float4* Wk4 = (const float4*)Wk;
        float acc[8];
        #pragma unroll
        for (int j = 0; j < 8; j++) acc[j] = 0.f;
        float ubacc = 0.f;
        for (int e0 = 0; e0 < 2; e0++) {           // e-chunks of 64
            #pragma unroll
            for (int k = 0; k < 8; k++) {
                int i = tid + k * 256;
                int dd = i >> 4, eq = i & 15;
                wq4s[dd * 17 + eq] = Wq4[dd * 256 + h * 32 + e0 * 16 + eq];
            }
            {
                int r = tid >> 4, eq = tid & 15;
                wk4s[r * 16 + eq] = Wk4[(r0 + r) * 256 + h * 32 + e0 * 16 + eq];
            }
            if (rt == 0 && tid < 16)
                bk4s[tid] = ((const float4*)bk)[h * 32 + e0 * 16 + tid];
            __syncthreads();
            #pragma unroll 4
            for (int e4 = 0; e4 < 16; e4++) {
                float4 q4 = wq4s[d2 * 17 + e4];
                #pragma unroll
                for (int j = 0; j < 8; j++)
                    acc[j] += dot4(q4, wk4s[(rg * 8 + j) * 16 + e4]);
                if (rt == 0 && rg == 0) ubacc += dot4(q4, bk4s[e4]);
            }
            __syncthreads();
        }
        #pragma unroll
        for (int j = 0; j < 8; j++)
            g_G[h * 16384 + (r0 + rg * 8 + j) * DD + d2] = SCALE * acc[j];
        if (rt == 0 && rg == 0) g_ub[h * DD + d2] = SCALE * ubacc;
    } else if (blk < 128) {
        // ------------- M role: M[h, r0..r0+15, :] -------------
        const int w = blk - 64, h = w >> 3, r0 = (w & 7) * 16;
        const int d2 = tid & 127, rh = tid >> 7;
        float* wo_s = s;            // 64 x 128
        float* wv_s = s + 8192;     // 16 x 64
        float acc[8];
        #pragma unroll
        for (int j = 0; j < 8; j++) acc[j] = 0.f;
        for (int e0 = 0; e0 < 128; e0 += 64) {
            for (int i = tid; i < 8192; i += 256) {
                int e = i >> 7, dd = i & 127;
                wo_s[i] = Wo[(h * 128 + e0 + e) * DD + dd];
            }
            for (int i = tid; i < 1024; i += 256) {
                int r = i >> 6, e = i & 63;
                wv_s[i] = Wv[(r0 + r) * HE + h * 128 + e0 + e];
            }
            __syncthreads();
            #pragma unroll 8
            for (int e = 0; e < 64; e++) {
                float wo = wo_s[e * 128 + d2];
                #pragma unroll
                for (int j = 0; j < 8; j++)
                    acc[j] += wv_s[(rh * 8 + j) * 64 + e] * wo;
            }
            __syncthreads();
        }
        #pragma unroll
        for (int j = 0; j < 8; j++)
            g_M[(h * 128 + r0 + rh * 8 + j) * DD + d2] = acc[j];
    } else if (blk < 136) {
        // ------------- gb role: gb'[h, :] -------------
        const int h = blk - 128, eq = tid & 31, dg = tid >> 5;
        float4 bqv = ((const float4*)bq)[h * 32 + eq];
        const float4* Wk4 = (const float4*)Wk;
        #pragma unroll
        for (int i = 0; i < 16; i++) {
            int dd = dg * 16 + i;
            float p = dot4(Wk4[dd * 256 + h * 32 + eq], bqv);
            #pragma unroll
            for (int o = 16; o > 0; o >>= 1)
                p += __shfl_xor_sync(0xffffffffu, p, o);
            if (eq == 0) g_gb[h * DD + dd] = SCALE * p;
        }
    } else if (blk < 144) {
        // ------------- cbias partial: k-slice p -------------
        const int p = blk - 136, d2 = tid & 127, kh = tid >> 7;
        float acc = 0.f;
        #pragma unroll 8
        for (int i = 0; i < 64; i++) {
            int k = p * 128 + kh * 64 + i;
            acc += __ldg(bv + k) * Wo[k * DD + d2];
        }
        s[tid] = acc;
        __syncthreads();
        if (kh == 0)
            g_cbp[p * DD + d2] = s[d2] + s[128 + d2] + (p == 0 ? bo[d2] : 0.f);
    } else {
        // ------------- misc: S, dq' -------------
        s[tid] = Ws[tid];
        {
            int h = tid >> 5, lane = tid & 31;
            float p = dot4(((const float4*)bk)[h * 32 + lane],
                           ((const float4*)bq)[h * 32 + lane]);
            #pragma unroll
            for (int o = 16; o > 0; o >>= 1)
                p += __shfl_xor_sync(0xffffffffu, p, o);
            if (lane == 0) g_dqs[h] = SCALE * p;
        }
        __syncthreads();
        for (int st = 128; st > 0; st >>= 1) {
            if (tid < st) s[tid] += s[tid + st];
            __syncthreads();
        }
        if (tid == 0) g_S = s[0];
    }
}

// ===========================================================================
// K2: one CTA per batch.  grid 64 x 1024 thr, 189984 B dynamic smem.
//
// smem float offsets (all vector-accessed bases 16B-aligned):
#define SX_PAD  132
#define OSX   0        // sx [256 t][132 d pad]   33792
#define OWS   33792    // Ws                      256
#define OXS   34048    // xs                      128
#define OSU   34176    // su [128 d][8 h] / sy    1024
#define OSC   35200    // c[8]                    8
#define OBH   35208    // scores [h][256 t]       2048
#define OBT   37256    // beta   [256 t][8 h]     2048
#define OPART 39304    // scratch partials        8192
#define K2_FLOATS 47496

extern "C" __global__ __launch_bounds__(1024, 1)
void k_main(const float* __restrict__ x, const float* __restrict__ Ws,
            const float* __restrict__ bs, float* __restrict__ out)
{
    extern __shared__ __align__(16) float sm[];
    float* sx     = sm + OSX;
    float* sWs    = sm + OWS;
    float* xs_f   = sm + OXS;
    float* su     = sm + OSU;     // later reused as sy
    float* sc     = sm + OSC;
    float* sbetaH = sm + OBH;
    float* sbetaT = sm + OBT;
    float* spart  = sm + OPART;

    const int tid = threadIdx.x;
    const int b = blockIdx.x;

    // ---- phase 0 (overlaps k_pre under PDL): x tile [t][d] + xs partials ----
    if (tid < 256) sWs[tid] = Ws[tid];
    __syncthreads();
    {
        const int d = tid & 127, tg = tid >> 7;   // 8 t-groups of 32
        const float* xb = x + ((size_t)b * TT) * DD + d;
        float acc = 0.f;
        #pragma unroll
        for (int k = 0; k < 32; k++) {
            int t = k * 8 + tg;
            float v = xb[t * DD];
            sx[t * SX_PAD + d] = v;
            acc += sWs[t] * v;
        }
        spart[tg * 128 + d] = acc;
    }
    __syncthreads();
    if (tid < 128) {
        float v = 0.f;
        #pragma unroll
        for (int g = 0; g < 8; g++) v += spart[g * 128 + tid];
        xs_f[tid] = v;
    }
    __syncthreads();

    // first use of k_pre outputs — wait for its grid now
    cudaGridDependencySynchronize();
    const float S = g_S;

    // ---- phase 1: c[h] (warps 0-7) and u partials (all threads) ----
    if (tid < 256) {
        int h = tid >> 5, lane = tid & 31;
        float p = dot4(((const float4*)xs_f)[lane],
                       ((const float4*)g_gb)[h * 32 + lane]);
        #pragma unroll
        for (int o = 16; o > 0; o >>= 1)
            p += __shfl_xor_sync(0xffffffffu, p, o);
        if (lane == 0) sc[h] = p + S * g_dqs[h] + bs[0];
    }
    {   // u partial: h = tid>>7, f4 = tid&31, strip = (tid>>5)&3 (32 dp each)
        const int h = tid >> 7, f4 = tid & 31, strip = (tid >> 5) & 3;
        const float4* G4 = (const float4*)g_G + h * 4096 + f4;
        float4 acc = make_float4(0.f, 0.f, 0.f, 0.f);
        #pragma unroll
        for (int i = 0; i < 32; i++) {
            int dp = strip * 32 + i;
            float xv = xs_f[dp];
            float4 gv = G4[dp * 32];
            acc.x += xv * gv.x; acc.y += xv * gv.y;
            acc.z += xv * gv.z; acc.w += xv * gv.w;
        }
        // partial id (within strip plane) = h*32+f4; planes stride 1024 floats
        ((float4*)spart)[strip * 256 + h * 32 + f4] = acc;
    }
    __syncthreads();
    {   // reduce 4 strips -> su[d*8+h] (+ S*ub)
        const int h = tid >> 7, d = tid & 127;
        const int o = h * 128 + d;   // == (h*32 + (d>>2))*4 + (d&3)
        float v = spart[o] + spart[1024 + o] + spart[2048 + o] + spart[3072 + o];
        su[d * 8 + h] = v + S * g_ub[o];
    }
    __syncthreads();

    // ---- phase 2: summary scores; thread = (t = tid&255, dq = tid>>8) ----
    {
        const int t = tid & 255, dq = tid >> 8;   // 4 chunks of 32 d
        unsigned long long a0 = 0, a1 = 0, a2 = 0, a3 = 0;
        const float4* xrow = (const float4*)(sx + t * SX_PAD + dq * 32);
        #pragma unroll
        for (int i4 = 0; i4 < 8; i4++) {
            float4 xv4 = xrow[i4];
            const int d0 = dq * 32 + i4 * 4;
            #pragma unroll
            for (int j = 0; j < 4; j++) {
                float xv = j == 0 ? xv4.x : (j == 1 ? xv4.y : (j == 2 ? xv4.z : xv4.w));
                unsigned long long xp = pk2(xv, xv);
                const ulonglong2* up = (const ulonglong2*)(su + (d0 + j) * 8);
                ulonglong2 u01 = up[0], u23 = up[1];
                ffma2(a0, u01.x, xp); ffma2(a1, u01.y, xp);
                ffma2(a2, u23.x, xp); ffma2(a3, u23.y, xp);
            }
        }
        float2 f0 = upk2(a0), f1 = upk2(a1), f2 = upk2(a2), f3 = upk2(a3);
        // partials: spart[h*1024 + dq*256 + t] — lanes (t) consecutive
        float* pp = spart + dq * 256 + t;
        pp[0]        = f0.x; pp[1024]     = f0.y;
        pp[2 * 1024] = f1.x; pp[3 * 1024] = f1.y;
        pp[4 * 1024] = f2.x; pp[5 * 1024] = f2.y;
        pp[6 * 1024] = f3.x; pp[7 * 1024] = f3.y;
    }
    __syncthreads();
    #pragma unroll
    for (int k = 0; k < 2; k++) {   // reduce dq -> sbetaH[h*256+t]
        int i = tid + k * 1024;     // i = h*256 + t
        int h = i >> 8, t = i & 255;
        const float* pp = spart + h * 1024 + t;
        sbetaH[i] = pp[0] + pp[256] + pp[512] + pp[768] + sc[h];
    }
    __syncthreads();

    // ---- phase 3: full softmax over t (warp per head); write beta [t][h] ----
    if (tid < 256) {
        int h = tid >> 5, lane = tid & 31;
        float v[8];
        float m = -1e30f;
        #pragma unroll
        for (int i = 0; i < 8; i++) {
            v[i] = sbetaH[h * 256 + lane + 32 * i];
            m = fmaxf(m, v[i]);
        }
        #pragma unroll
        for (int o = 16; o > 0; o >>= 1)
            m = fmaxf(m, __shfl_xor_sync(0xffffffffu, m, o));
        float ss = 0.f;
        #pragma unroll
        for (int i = 0; i < 8; i++) { v[i] = __expf(v[i] - m); ss += v[i]; }
        #pragma unroll
        for (int o = 16; o > 0; o >>= 1)
            ss += __shfl_xor_sync(0xffffffffu, ss, o);
        float inv = 1.f / ss;
        #pragma unroll
        for (int i = 0; i < 8; i++)
            sbetaT[(lane + 32 * i) * 8 + h] = v[i] * inv;
    }
    __syncthreads();

    // ---- phase 4: y partials; thread = (d = tid&127, tg = tid>>7 of 8) ----
    {
        const int d = tid & 127, tg = tid >> 7;
        unsigned long long a0 = 0, a1 = 0, a2 = 0, a3 = 0;
        #pragma unroll
        for (int i = 0; i < 32; i++) {
            int t = tg * 32 + i;
            float xv = sx[t * SX_PAD + d];
            unsigned long long xp = pk2(xv, xv);
            const ulonglong2* bp = (const ulonglong2*)(sbetaT + t * 8);
            ulonglong2 b01 = bp[0], b23 = bp[1];
            ffma2(a0, b01.x, xp); ffma2(a1, b01.y, xp);
            ffma2(a2, b23.x, xp); ffma2(a3, b23.y, xp);
        }
        float2 v0 = upk2(a0), v1 = upk2(a1), v2 = upk2(a2), v3 = upk2(a3);
        float* pg = spart + tg * 1024;
        pg[0 * 128 + d] = v0.x; pg[1 * 128 + d] = v0.y;
        pg[2 * 128 + d] = v1.x; pg[3 * 128 + d] = v1.y;
        pg[4 * 128 + d] = v2.x; pg[5 * 128 + d] = v2.y;
        pg[6 * 128 + d] = v3.x; pg[7 * 128 + d] = v3.y;
    }
    __syncthreads();
    {   // reduce 8 t-groups -> sy (reuse su)
        float v = 0.f;
        #pragma unroll
        for (int g = 0; g < 8; g++) v += spart[g * 1024 + tid];
        su[tid] = v;   // su now holds y[k], k = h*128+d
    }
    __syncthreads();

    // ---- phase 5: out = y @ M; thread = (f4 = tid&31, kg = tid>>5 of 32) ----
    {
        const int f4 = tid & 31, kg = tid >> 5;
        const float4* M4 = (const float4*)g_M + (kg * 32) * 32 + f4;
        float4 acc = make_float4(0.f, 0.f, 0.f, 0.f);
        #pragma unroll
        for (int kk = 0; kk < 32; kk++) {
            float yk = su[kg * 32 + kk];
            float4 mv = M4[kk * 32];
            acc.x += yk * mv.x; acc.y += yk * mv.y;
            acc.z += yk * mv.z; acc.w += yk * mv.w;
        }
        ((float4*)spart)[kg * 32 + f4] = acc;
    }
    __syncthreads();
    if (tid < 128) {
        float o = 0.f;
        #pragma unroll
        for (int p = 0; p < 8; p++) o += g_cbp[p * DD + tid];
        #pragma unroll
        for (int kg = 0; kg < 32; kg++) o += spart[kg * 128 + tid];
        out[b * DD + tid] = o;
    }
}

// ===========================================================================
extern "C" void kernel_launch(void* const* d_in, const int* in_sizes, int n_in,
                              void* d_out, int out_size) {
    const float* x  = (const float*)d_in[0];
    const float* Wq = (const float*)d_in[1];
    const float* bq = (const float*)d_in[2];
    const float* Wk = (const float*)d_in[3];
    const float* bk = (const float*)d_in[4];
    const float* Wv = (const float*)d_in[5];
    const float* bv = (const float*)d_in[6];
    const float* Ws = (const float*)d_in[7];
    const float* bs = (const float*)d_in[8];
    const float* Wo = (const float*)d_in[9];
    const float* bo = (const float*)d_in[10];
    float* out = (float*)d_out;

    static bool attr_done = false;
    if (!attr_done) {
        cudaFuncSetAttribute(k_main, cudaFuncAttributeMaxDynamicSharedMemorySize,
                             K2_FLOATS * 4);
        attr_done = true;
    }

    k_pre<<<145, 256>>>(Ws, Wk, bk, Wq, bq, Wv, bv, Wo, bo);

    // k_main with PDL: k_pre triggers launch-completion at entry, so k_main's
    // phase 0 (x fill + xs) overlaps k_pre; gridDepSync gates first G/S use.
    cudaLaunchConfig_t cfg = {};
    cfg.gridDim = dim3(64, 1, 1);
    cfg.blockDim = dim3(1024, 1, 1);
    cfg.dynamicSmemBytes = K2_FLOATS * 4;
    cfg.stream = 0;
    cudaLaunchAttribute attrs[1];
    attrs[0].id = cudaLaunchAttributeProgrammaticStreamSerialization;
    attrs[0].val.programmaticStreamSerializationAllowed = 1;
    cfg.attrs = attrs;
    cfg.numAttrs = 1;
    cudaLaunchKernelEx(&cfg, k_main, x, Ws, bs, out);
}

// round 13
// speedup vs baseline: 1.0809x; 1.0809x over previous
#include <cuda_runtime.h>
#include <cstdint>

// Temporal_Attention — weight-space-collapsed, head-split.
// k_pre: weight-only precompute (G', ub', gb', dq', M, cbias, S); PDL trigger
//        at entry so k_main overlaps it.
// k_main: 2 CTAs per batch (cluster 2), each owns 4 HEADS. grid 128 x 1024
//         thr, ~160 KB smem, 1 CTA/SM uniform. Softmax fully CTA-local;
//         single DSMEM exchange (out partials) at the end.
// B=64, T=256, D=128, H=8, E=128.  out[B,D] fp32.

#define BB 64
#define TT 256
#define DD 128
#define HH 8
#define HE 1024
#define SCALE 0.088388347648318447f

static __device__ float g_S;
static __device__ __align__(16) float g_G[HH * DD * DD];   // [h][dp][d]
static __device__ __align__(16) float g_ub[HH * DD];
static __device__ __align__(16) float g_gb[HH * DD];
static __device__ float g_dqs[HH];
static __device__ __align__(16) float g_M[HE * DD];        // [k][d2]
static __device__ __align__(16) float g_cbp[8 * DD];

// ---- helpers ---------------------------------------------------------------
__device__ __forceinline__ void ffma2(unsigned long long& d,
                                      unsigned long long a, unsigned long long b) {
    asm("fma.rn.f32x2 %0, %1, %2, %0;" : "+l"(d) : "l"(a), "l"(b));
}
__device__ __forceinline__ unsigned long long pk2(float x, float y) {
    unsigned long long r;
    asm("mov.b64 %0, {%1, %2};" : "=l"(r) : "f"(x), "f"(y));
    return r;
}
__device__ __forceinline__ float2 upk2(unsigned long long v) {
    float lo, hi;
    asm("mov.b64 {%0, %1}, %2;" : "=f"(lo), "=f"(hi) : "l"(v));
    return make_float2(lo, hi);
}
__device__ __forceinline__ float dot4(float4 a, float4 b) {
    return a.x * b.x + a.y * b.y + a.z * b.z + a.w * b.w;
}
__device__ __forceinline__ uint32_t smem_u32(const void* p) {
    uint32_t a;
    asm("{ .reg .u64 t; cvta.to.shared.u64 t, %1; cvt.u32.u64 %0, t; }"
        : "=r"(a) : "l"(p));
    return a;
}
__device__ __forceinline__ uint32_t mapa_rank(uint32_t addr, uint32_t rank) {
    uint32_t r;
    asm("mapa.shared::cluster.u32 %0, %1, %2;" : "=r"(r) : "r"(addr), "r"(rank));
    return r;
}
__device__ __forceinline__ float ld_dsmem(uint32_t a) {
    float v;
    asm volatile("ld.shared::cluster.f32 %0, [%1];" : "=f"(v) : "r"(a));
    return v;
}
#define CLUSTER_SYNC() do { \
    asm volatile("barrier.cluster.arrive.aligned;" ::: "memory"); \
    asm volatile("barrier.cluster.wait.aligned;" ::: "memory"); \
} while (0)

// ===========================================================================
// K1: grid 145 x 256.  roles: G(0-63) | M(64-127) | gb(128-135)
//                             | cbias(136-143) | misc(144)
__global__ __launch_bounds__(256) void k_pre(
    const float* __restrict__ Ws,
    const float* __restrict__ Wk, const float* __restrict__ bk,
    const float* __restrict__ Wq, const float* __restrict__ bq,
    const float* __restrict__ Wv, const float* __restrict__ bv,
    const float* __restrict__ Wo, const float* __restrict__ bo)
{
    cudaTriggerProgrammaticLaunchCompletion();

    __shared__ __align__(16) float s[12288];   // 48 KB
    const int blk = blockIdx.x, tid = threadIdx.x;

    if (blk < 64) {
        // ------------- G role: G'[h, r0..r0+15, :] (+ub on rt==0) -------------
        const int w = blk, h = w >> 3, rt = w & 7, r0 = rt * 16;
        const int d2 = tid & 127, rg = tid >> 7;
        float4* wq4s = (float4*)s;            // [128][17] float4
        float4* wk4s = (float4*)(s + 8704);   // [16][16]
        float4* bk4s = (float4*)(s + 9728);   // [16]
        const float4* Wq4 = (const float4*)Wq;
        const float4* Wk4 = (const float4*)Wk;
        float acc[8];
        #pragma unroll
        for (int j = 0; j < 8; j++) acc[j] = 0.f;
        float ubacc = 0.f;
        for (int e0 = 0; e0 < 2; e0++) {           // e-chunks of 64
            #pragma unroll
            for (int k = 0; k < 8; k++) {
                int i = tid + k * 256;
                int dd = i >> 4, eq = i & 15;
                wq4s[dd * 17 + eq] = Wq4[dd * 256 + h * 32 + e0 * 16 + eq];
            }
            {
                int r = tid >> 4, eq = tid & 15;
                wk4s[r * 16 + eq] = Wk4[(r0 + r) * 256 + h * 32 + e0 * 16 + eq];
            }
            if (rt == 0 && tid < 16)
                bk4s[tid] = ((const float4*)bk)[h * 32 + e0 * 16 + tid];
            __syncthreads();
            #pragma unroll 4
            for (int e4 = 0; e4 < 16; e4++) {
                float4 q4 = wq4s[d2 * 17 + e4];
                #pragma unroll
                for (int j = 0; j < 8; j++)
                    acc[j] += dot4(q4, wk4s[(rg * 8 + j) * 16 + e4]);
                if (rt == 0 && rg == 0) ubacc += dot4(q4, bk4s[e4]);
            }
            __syncthreads();
        }
        #pragma unroll
        for (int j = 0; j < 8; j++)
            g_G[h * 16384 + (r0 + rg * 8 + j) * DD + d2] = SCALE * acc[j];
        if (rt == 0 && rg == 0) g_ub[h * DD + d2] = SCALE * ubacc;
    } else if (blk < 128) {
        // ------------- M role: M[h, r0..r0+15, :] -------------
        const int w = blk - 64, h = w >> 3, r0 = (w & 7) * 16;
        const int d2 = tid & 127, rh = tid >> 7;
        float* wo_s = s;            // 64 x 128
        float* wv_s = s + 8192;     // 16 x 64
        float acc[8];
        #pragma unroll
        for (int j = 0; j < 8; j++) acc[j] = 0.f;
        for (int e0 = 0; e0 < 128; e0 += 64) {
            for (int i = tid; i < 8192; i += 256) {
                int e = i >> 7, dd = i & 127;
                wo_s[i] = Wo[(h * 128 + e0 + e) * DD + dd];
            }
            for (int i = tid; i < 1024; i += 256) {
                int r = i >> 6, e = i & 63;
                wv_s[i] = Wv[(r0 + r) * HE + h * 128 + e0 + e];
            }
            __syncthreads();
            #pragma unroll 8
            for (int e = 0; e < 64; e++) {
                float wo = wo_s[e * 128 + d2];
                #pragma unroll
                for (int j = 0; j < 8; j++)
                    acc[j] += wv_s[(rh * 8 + j) * 64 + e] * wo;
            }
            __syncthreads();
        }
        #pragma unroll
        for (int j = 0; j < 8; j++)
            g_M[(h * 128 + r0 + rh * 8 + j) * DD + d2] = acc[j];
    } else if (blk < 136) {
        // ------------- gb role: gb'[h, :] -------------
        const int h = blk - 128, eq = tid & 31, dg = tid >> 5;
        float4 bqv = ((const float4*)bq)[h * 32 + eq];
        const float4* Wk4 = (const float4*)Wk;
        #pragma unroll
        for (int i = 0; i < 16; i++) {
            int dd = dg * 16 + i;
            float p = dot4(Wk4[dd * 256 + h * 32 + eq], bqv);
            #pragma unroll
            for (int o = 16; o > 0; o >>= 1)
                p += __shfl_xor_sync(0xffffffffu, p, o);
            if (eq == 0) g_gb[h * DD + dd] = SCALE * p;
        }
    } else if (blk < 144) {
        // ------------- cbias partial: k-slice p -------------
        const int p = blk - 136, d2 = tid & 127, kh = tid >> 7;
        float acc = 0.f;
        #pragma unroll 8
        for (int i = 0; i < 64; i++) {
            int k = p * 128 + kh * 64 + i;
            acc += __ldg(bv + k) * Wo[k * DD + d2];
        }
        s[tid] = acc;
        __syncthreads();
        if (kh == 0)
            g_cbp[p * DD + d2] = s[d2] + s[128 + d2] + (p == 0 ? bo[d2] : 0.f);
    } else {
        // ------------- misc: S, dq' -------------
        s[tid] = Ws[tid];
        {
            int h = tid >> 5, lane = tid & 31;
            float p = dot4(((const float4*)bk)[h * 32 + lane],
                           ((const float4*)bq)[h * 32 + lane]);
            #pragma unroll
            for (int o = 16; o > 0; o >>= 1)
                p += __shfl_xor_sync(0xffffffffu, p, o);
            if (lane == 0) g_dqs[h] = SCALE * p;
        }
        __syncthreads();
        for (int st = 128; st > 0; st >>= 1) {
            if (tid < st) s[tid] += s[tid + st];
            __syncthreads();
        }
        if (tid == 0) g_S = s[0];
    }
}

// ===========================================================================
// K2: 2 CTAs per batch (cluster 2); rank r owns heads 4r..4r+3.
//   grid 128 x 1024 thr, ~160 KB dynamic smem, 1 CTA/SM.
//
// smem float offsets:
#define SX_PAD  132
#define OSX   0        // sx [256 t][132 d pad]   33792
#define OWS   33792    // Ws                      256
#define OXS   34048    // xs                      128
#define OSU   34176    // su [128 d][4 h] / sy    512
#define OSC   34688    // c[4] (pad 8)            8
#define OSCO  34696    // scores [4 h][256 t]     1024
#define OBT   35720    // beta [256 t][4 h]       1024
#define OPART 36744    // scratch partials        4096
#define OSOUT 40840    // out partial (128 d2)    128
#define K2_FLOATS 40968

extern "C" __global__ __launch_bounds__(1024, 1) __cluster_dims__(2, 1, 1)
void k_main(const float* __restrict__ x, const float* __restrict__ Ws,
            const float* __restrict__ bs, float* __restrict__ out)
{
    extern __shared__ __align__(16) float sm[];
    float* sx    = sm + OSX;
    float* sWs   = sm + OWS;
    float* xs_f  = sm + OXS;
    float* su    = sm + OSU;     // later reused as sy
    float* sc    = sm + OSC;
    float* sco   = sm + OSCO;
    float* sbeta = sm + OBT;
    float* spart = sm + OPART;
    float* sout  = sm + OSOUT;

    const int tid = threadIdx.x;
    uint32_t rank;
    asm("mov.u32 %0, %%cluster_ctarank;" : "=r"(rank));
    const int r = (int)rank;
    const uint32_t peer = 1u - rank;
    const int b = blockIdx.x >> 1;

    // ---- phase 0 (overlaps k_pre under PDL): full x tile + xs (redundant) ----
    if (tid < 256) sWs[tid] = Ws[tid];
    __syncthreads();
    {
        const int d = tid & 127, tg = tid >> 7;   // 8 t-groups of 32
        const float* xb = x + ((size_t)b * TT) * DD + d;
        float acc = 0.f;
        #pragma unroll
        for (int k = 0; k < 32; k++) {
            int t = k * 8 + tg;
            float v = xb[t * DD];
            sx[t * SX_PAD + d] = v;
            acc += sWs[t] * v;
        }
        spart[tg * 128 + d] = acc;
    }
    __syncthreads();
    if (tid < 128) {
        float v = 0.f;
        #pragma unroll
        for (int g = 0; g < 8; g++) v += spart[g * 128 + tid];
        xs_f[tid] = v;
    }
    __syncthreads();

    // first use of k_pre outputs — wait for its grid now
    cudaGridDependencySynchronize();
    const float S = g_S;

    // ---- phase 1: u for own 4 heads (float4 G loads) ----
    {   // h_l = tid>>8, strip = (tid>>5)&7 (8 x 16 dp), f4 = tid&31
        const int h_l = tid >> 8, strip = (tid >> 5) & 7, f4 = tid & 31;
        const int hg = 4 * r + h_l;
        const float4* G4 = (const float4*)g_G + hg * 4096 + f4;
        float4 acc = make_float4(0.f, 0.f, 0.f, 0.f);
        #pragma unroll
        for (int i = 0; i < 16; i++) {
            int dp = strip * 16 + i;
            float xv = xs_f[dp];
            float4 gv = G4[dp * 32];
            acc.x += xv * gv.x; acc.y += xv * gv.y;
            acc.z += xv * gv.z; acc.w += xv * gv.w;
        }
        ((float4*)spart)[strip * 128 + h_l * 32 + f4] = acc;
    }
    __syncthreads();
    if (tid < 512) {   // reduce 8 strips -> su[d*4 + h_l] (+ S*ub)
        const int h_l = tid >> 7, d = tid & 127;
        const int hg = 4 * r + h_l;
        const int o = h_l * 128 + d;
        float v = 0.f;
        #pragma unroll
        for (int s = 0; s < 8; s++) v += spart[s * 512 + o];
        su[d * 4 + h_l] = v + S * g_ub[hg * 128 + d];
    } else if (tid < 640) {   // c for own 4 heads
        int h_l = (tid - 512) >> 5, lane = tid & 31;
        int hg = 4 * r + h_l;
        float p = dot4(((const float4*)xs_f)[lane],
                       ((const float4*)g_gb)[hg * 32 + lane]);
        #pragma unroll
        for (int o = 16; o > 0; o >>= 1)
            p += __shfl_xor_sync(0xffffffffu, p, o);
        if (lane == 0) sc[h_l] = p + S * g_dqs[hg] + bs[0];
    }
    __syncthreads();

    // ---- phase 2: summary for own 4 heads; thread (t = tid&255, dq = tid>>8) ----
    {
        const int t = tid & 255, dq = tid >> 8;   // 4 chunks of 32 d
        float xr[32];
        const float4* xrow = (const float4*)(sx + t * SX_PAD + dq * 32);
        #pragma unroll
        for (int i = 0; i < 8; i++) {
            float4 v = xrow[i];
            xr[i * 4 + 0] = v.x; xr[i * 4 + 1] = v.y;
            xr[i * 4 + 2] = v.z; xr[i * 4 + 3] = v.w;
        }
        unsigned long long a0 = 0, a1 = 0;
        #pragma unroll
        for (int i = 0; i < 32; i++) {
            int d = dq * 32 + i;
            unsigned long long xp = pk2(xr[i], xr[i]);
            const ulonglong2* up = (const ulonglong2*)(su + d * 4);
            ulonglong2 u4 = *up;
            ffma2(a0, u4.x, xp);
            ffma2(a1, u4.y, xp);
        }
        float2 f0 = upk2(a0), f1 = upk2(a1);
        float* pp = spart + dq * 1024 + t;
        pp[0]   = f0.x; pp[256] = f0.y;
        pp[512] = f1.x; pp[768] = f1.y;
    }
    __syncthreads();
    {   // reduce dq -> sco[h_l*256 + t]
        int h_l = tid >> 8, t = tid & 255;
        const float* pp = spart + h_l * 256 + t;
        sco[tid] = pp[0] + pp[1024] + pp[2048] + pp[3072] + sc[h_l];
    }
    __syncthreads();

    // ---- phase 3: full softmax over t (warp per own head), CTA-local ----
    if (tid < 128) {
        int h_l = tid >> 5, lane = tid & 31;
        float v[8];
        float m = -1e30f;
        #pragma unroll
        for (int i = 0; i < 8; i++) {
            v[i] = sco[h_l * 256 + lane + 32 * i];
            m = fmaxf(m, v[i]);
        }
        #pragma unroll
        for (int o = 16; o > 0; o >>= 1)
            m = fmaxf(m, __shfl_xor_sync(0xffffffffu, m, o));
        float ss = 0.f;
        #pragma unroll
        for (int i = 0; i < 8; i++) { v[i] = __expf(v[i] - m); ss += v[i]; }
        #pragma unroll
        for (int o = 16; o > 0; o >>= 1)
            ss += __shfl_xor_sync(0xffffffffu, ss, o);
        float inv = 1.f / ss;
        #pragma unroll
        for (int i = 0; i < 8; i++)
            sbeta[(lane + 32 * i) * 4 + h_l] = v[i] * inv;
    }
    __syncthreads();

    // ---- phase 4: y for own heads; thread (d = tid&127, tg = tid>>7 of 8) ----
    {
        const int d = tid & 127, tg = tid >> 7;
        unsigned long long a0 = 0, a1 = 0;
        #pragma unroll
        for (int i = 0; i < 32; i++) {
            int t = tg * 32 + i;
            float xv = sx[t * SX_PAD + d];
            unsigned long long xp = pk2(xv, xv);
            ulonglong2 b4 = *(const ulonglong2*)(sbeta + t * 4);
            ffma2(a0, b4.x, xp);
            ffma2(a1, b4.y, xp);
        }
        float2 v0 = upk2(a0), v1 = upk2(a1);
        float* pg = spart + tg * 512;
        pg[0 * 128 + d] = v0.x; pg[1 * 128 + d] = v0.y;
        pg[2 * 128 + d] = v1.x; pg[3 * 128 + d] = v1.y;
    }
    __syncthreads();
    if (tid < 512) {   // reduce 8 t-groups -> sy (reuse su); idx = h_l*128+d
        float v = 0.f;
        #pragma unroll
        for (int g = 0; g < 8; g++) v += spart[g * 512 + tid];
        su[tid] = v;
    }
    __syncthreads();

    // ---- phase 5: out partial over own 512 M rows (float4 M loads) ----
    {
        const int f4 = tid & 31, kg = tid >> 5;   // 32 groups of 16 k
        const float4* M4 = (const float4*)g_M + ((size_t)r * 512 + kg * 16) * 32 + f4;
        float4 acc = make_float4(0.f, 0.f, 0.f, 0.f);
        #pragma unroll
        for (int kk = 0; kk < 16; kk++) {
            float yk = su[kg * 16 + kk];
            float4 mv = M4[kk * 32];
            acc.x += yk * mv.x; acc.y += yk * mv.y;
            acc.z += yk * mv.z; acc.w += yk * mv.w;
        }
        ((float4*)spart)[kg * 32 + f4] = acc;
    }
    __syncthreads();
    if (tid < 128) {
        float v = 0.f;
        #pragma unroll
        for (int kg = 0; kg < 32; kg++) v += spart[kg * 128 + tid];
        sout[tid] = v;
    }
    CLUSTER_SYNC();   // #1: out partials visible cluster-wide
    if (tid < 64) {
        int d2 = r * 64 + tid;
        float o = 0.f;
        #pragma unroll
        for (int p = 0; p < 8; p++) o += g_cbp[p * DD + d2];
        o += sout[d2] + ld_dsmem(mapa_rank(smem_u32(sout + d2), peer));
        out[b * DD + d2] = o;
    }
    CLUSTER_SYNC();   // #2: exit guard
}

// ===========================================================================
extern "C" void kernel_launch(void* const* d_in, const int* in_sizes, int n_in,
                              void* d_out, int out_size) {
    const float* x  = (const float*)d_in[0];
    const float* Wq = (const float*)d_in[1];
    const float* bq = (const float*)d_in[2];
    const float* Wk = (const float*)d_in[3];
    const float* bk = (const float*)d_in[4];
    const float* Wv = (const float*)d_in[5];
    const float* bv = (const float*)d_in[6];
    const float* Ws = (const float*)d_in[7];
    const float* bs = (const float*)d_in[8];
    const float* Wo = (const float*)d_in[9];
    const float* bo = (const float*)d_in[10];
    float* out = (float*)d_out;

    static bool attr_done = false;
    if (!attr_done) {
        cudaFuncSetAttribute(k_main, cudaFuncAttributeMaxDynamicSharedMemorySize,
                             K2_FLOATS * 4);
        attr_done = true;
    }

    k_pre<<<145, 256>>>(Ws, Wk, bk, Wq, bq, Wv, bv, Wo, bo);

    // k_main with PDL: k_pre triggers launch-completion at entry, so k_main's
    // phase 0 (x fill + xs) overlaps k_pre; gridDepSync gates first G/S use.
    cudaLaunchConfig_t cfg = {};
    cfg.gridDim = dim3(128, 1, 1);
    cfg.blockDim = dim3(1024, 1, 1);
    cfg.dynamicSmemBytes = K2_FLOATS * 4;
    cfg.stream = 0;
    cudaLaunchAttribute attrs[2];
    attrs[0].id = cudaLaunchAttributeProgrammaticStreamSerialization;
    attrs[0].val.programmaticStreamSerializationAllowed = 1;
    attrs[1].id = cudaLaunchAttributeClusterDimension;
    attrs[1].val.clusterDim = {2, 1, 1};
    cfg.attrs = attrs;
    cfg.numAttrs = 2;
    cudaLaunchKernelEx(&cfg, k_main, x, Ws, bs, out);
}